// round 2
// baseline (speedup 1.0000x reference)
#include <cuda_runtime.h>
#include <math.h>

#define BB 4
#define HH 192
#define WW 192
#define CC 64
#define HO 186
#define BHW (BB*HH*WW)          /* 147456 */
#define NELEM (BB*HH*WW*CC)     /* 9437184 */

// ---------------- scratch (device globals; no allocs allowed) ----------------
__device__ float  g_X[3][NELEM];            // x-conv results, orders 0..2 (reused per sigma)
__device__ float  g_P[2*10*2*BHW];          // [sigma][entry][chalf][b*H*W] channel-reduced products
__device__ float4 g_fx4[2][13];             // x-factors per sigma: (ord0, ord1, ord2, pad) per tap
__device__ float  g_fy8[2][13*8];           // y-factors packed per tap: [m0,m1,m3,m2,m4,m5,0,0]
__device__ float  g_w2[49];                 // integrator 7x7 = wy[i]*wx[j]

// ---------------- factorization of the 2-D kernels into 1-D factors ----------
__device__ void factor_one(const float* K, int Ksz, int s) {
    const int canon[3] = {0, 2, 5};          // canonical kernel per x-order (k=0,1,2)
    const int kxo[6]   = {0, 0, 1, 0, 1, 2}; // x-order of kernel m
    int   c0s[3];
    float fx[3][13];
    for (int o = 0; o < 3; ++o) {
        const float* Km = K + canon[o]*Ksz*Ksz*CC;
        int r0 = 0, c0 = 0; float best = -1.f;
        for (int i = 0; i < Ksz; ++i)
            for (int j = 0; j < Ksz; ++j) {
                float v = fabsf(Km[(i*Ksz + j)*CC]);
                if (v > best) { best = v; r0 = i; c0 = j; }
            }
        float piv = Km[(r0*Ksz + c0)*CC];
        for (int j = 0; j < Ksz; ++j) fx[o][j] = Km[(r0*Ksz + j)*CC] / piv;
        c0s[o] = c0;
    }
    for (int j = 0; j < Ksz; ++j)
        g_fx4[s][j] = make_float4(fx[0][j], fx[1][j], fx[2][j], 0.f);

    const float comb[6] = {1.f, 1.f, 1.f, 1.f, 1.41421356237309515f, 1.f}; // sqrt(C(j,k))
    for (int i = 0; i < Ksz; ++i)
        for (int q = 0; q < 8; ++q) g_fy8[s][i*8 + q] = 0.f;
    for (int m = 0; m < 6; ++m) {
        int c0 = c0s[kxo[m]];
        int slot = (m == 0) ? 0 : (m == 1) ? 1 : (m == 3) ? 2 : (m == 2) ? 3 : (m == 4) ? 4 : 5;
        for (int i = 0; i < Ksz; ++i)
            g_fy8[s][i*8 + slot] = K[(m*Ksz*Ksz + i*Ksz + c0)*CC] * comb[m];
    }
}

__global__ void factorize(const float* __restrict__ k0, const float* __restrict__ k1,
                          const float* __restrict__ dgi) {
    if (threadIdx.x != 0) return;
    factor_one(k0, 7, 0);
    factor_one(k1, 13, 1);
    // integrator: 7x7 rank-1, all channels identical (take c=0)
    int r0 = 0, c0 = 0; float best = -1.f;
    for (int i = 0; i < 7; ++i)
        for (int j = 0; j < 7; ++j) {
            float v = fabsf(dgi[(i*7 + j)*CC]);
            if (v > best) { best = v; r0 = i; c0 = j; }
        }
    float piv = dgi[(r0*7 + c0)*CC];
    for (int i = 0; i < 7; ++i)
        for (int j = 0; j < 7; ++j)
            g_w2[i*7 + j] = dgi[(i*7 + c0)*CC] * (dgi[(r0*7 + j)*CC] / piv);
}

// ---------------- stage 1: horizontal (x) convolution, orders 0..2 ----------
template<int R>
__global__ void __launch_bounds__(256) stage1(const float* __restrict__ in, int sigma) {
    constexpr int K  = 2*R + 1;
    constexpr int XT = 64;
    __shared__ float  s_in[(XT + 2*R)*CC];
    __shared__ float4 s_fx[K];
    const int b = blockIdx.z, y = blockIdx.y, x0 = blockIdx.x*XT;
    const int tid = threadIdx.x;
    if (tid < K) s_fx[tid] = g_fx4[sigma][tid];
    const float* row = in + ((size_t)(b*HH + y)*WW)*CC;
    for (int t = tid; t < (XT + 2*R)*CC; t += 256) {
        int xx = t / CC - R + x0;
        int c  = t - (t / CC)*CC;
        s_in[t] = (xx >= 0 && xx < WW) ? row[xx*CC + c] : 0.f;
    }
    __syncthreads();
    const int c = tid & 63, xg = tid >> 6;
    float* o0 = &g_X[0][((b*HH + y)*WW)*CC];
    float* o1 = &g_X[1][((b*HH + y)*WW)*CC];
    float* o2 = &g_X[2][((b*HH + y)*WW)*CC];
    for (int xq = 0; xq < XT/4; ++xq) {
        int xi = xg*(XT/4) + xq;
        float a0 = 0.f, a1 = 0.f, a2 = 0.f;
        #pragma unroll
        for (int t = 0; t < K; ++t) {
            float v = s_in[(xi + t)*CC + c];
            float4 f = s_fx[t];
            a0 = fmaf(f.x, v, a0);
            a1 = fmaf(f.y, v, a1);
            a2 = fmaf(f.z, v, a2);
        }
        int off = (x0 + xi)*CC + c;
        o0[off] = a0; o1[off] = a1; o2[off] = a2;
    }
}

// ---- stage 2: vertical conv (6 L maps) + outer products + channel reduce ----
// Thread = one (x, channel). Warp = 32 channels (one half of C); lane0 writes the
// warp's partial channel-sum; stage 3 adds the two halves. Register ring slides in y.
template<int R>
__global__ void __launch_bounds__(256) stage2(int sigma) {
    constexpr int K    = 2*R + 1;
    constexpr int SEGH = 48;
    __shared__ float s_cf[K*8];
    const int tid = threadIdx.x;
    if (tid < K*8) s_cf[tid] = g_fy8[sigma][tid];
    __syncthreads();
    const int warp  = tid >> 5, lane = tid & 31;
    const int xi    = warp >> 1, chalf = warp & 1;
    const int c     = chalf*32 + lane;
    const int b     = blockIdx.z;
    const int x     = blockIdx.x*4 + xi;
    const int ys    = blockIdx.y*SEGH;
    const int rs    = WW*CC;
    const size_t base = (size_t)b*HH*WW*CC + (size_t)x*CC + c;
    const float* X0 = &g_X[0][base];
    const float* X1 = &g_X[1][base];
    const float* X2 = &g_X[2][base];

    float r0[K], r1[K], r2[K];
    #pragma unroll
    for (int i = 0; i < K - 1; ++i) {
        int yy = ys - R + i;
        bool ok = (yy >= 0 && yy < HH);
        r0[i] = ok ? X0[yy*rs] : 0.f;
        r1[i] = ok ? X1[yy*rs] : 0.f;
        r2[i] = ok ? X2[yy*rs] : 0.f;
    }
    const float4* cf4 = (const float4*)s_cf;
    float* Pbase = &g_P[(size_t)(sigma*10*2 + chalf)*BHW + (size_t)b*HH*WW + x];

    for (int y = ys; y < ys + SEGH; ++y) {
        int yy = y + R;
        bool ok = yy < HH;
        r0[K-1] = ok ? X0[yy*rs] : 0.f;
        r1[K-1] = ok ? X1[yy*rs] : 0.f;
        r2[K-1] = ok ? X2[yy*rs] : 0.f;

        float L0 = 0.f, L1 = 0.f, L2 = 0.f, L3 = 0.f, L4 = 0.f, L5 = 0.f;
        #pragma unroll
        for (int i = 0; i < K; ++i) {
            float4 cA = cf4[i*2];
            float4 cB = cf4[i*2 + 1];
            L0 = fmaf(cA.x, r0[i], L0);
            L1 = fmaf(cA.y, r0[i], L1);
            L3 = fmaf(cA.z, r0[i], L3);
            L2 = fmaf(cA.w, r1[i], L2);
            L4 = fmaf(cB.x, r1[i], L4);
            L5 = fmaf(cB.y, r2[i], L5);
        }
        float p[10] = { L0*L0, L1*L1, L1*L2, L2*L2,
                        L3*L3, L3*L4, L3*L5, L4*L4, L4*L5, L5*L5 };
        #pragma unroll
        for (int off = 16; off >= 1; off >>= 1)
            #pragma unroll
            for (int e = 0; e < 10; ++e)
                p[e] += __shfl_xor_sync(0xffffffffu, p[e], off);
        if (lane == 0) {
            int py = y*WW;
            #pragma unroll
            for (int e = 0; e < 10; ++e)
                Pbase[(size_t)e*2*BHW + py] = p[e];
        }
        #pragma unroll
        for (int i = 0; i < K - 1; ++i) { r0[i] = r0[i+1]; r1[i] = r1[i+1]; r2[i] = r2[i+1]; }
    }
}

// ---------------- stage 3: 7x7 VALID integration + Newton-identity ESPs -----
__global__ void __launch_bounds__(256) stage3(float* __restrict__ out) {
    __shared__ float sP[20*22*22];
    __shared__ float sw[49];
    const int tid = threadIdx.x;
    const int b = blockIdx.z;
    const int y0 = blockIdx.y*16, x0 = blockIdx.x*16;
    if (tid < 49) sw[tid] = g_w2[tid];
    for (int idx = tid; idx < 20*484; idx += 256) {
        int se  = idx / 484;
        int rem = idx - se*484;
        int r   = rem / 22;
        int cc2 = rem - r*22;
        int y = y0 + r, x = x0 + cc2;
        float v = 0.f;
        if (y < HH && x < WW) {
            size_t pix = (size_t)(b*HH + y)*WW + x;
            v = g_P[(size_t)(se*2 + 0)*BHW + pix] + g_P[(size_t)(se*2 + 1)*BHW + pix];
        }
        sP[idx] = v;
    }
    __syncthreads();
    const int ty = tid >> 4, tx = tid & 15;
    const int yo = y0 + ty, xo = x0 + tx;
    if (yo >= HO || xo >= HO) return;

    float M[20];
    #pragma unroll
    for (int se = 0; se < 20; ++se) M[se] = 0.f;
    #pragma unroll
    for (int i = 0; i < 7; ++i)
        #pragma unroll
        for (int j = 0; j < 7; ++j) {
            float w = sw[i*7 + j];
            int o = (ty + i)*22 + (tx + j);
            #pragma unroll
            for (int se = 0; se < 20; ++se)
                M[se] = fmaf(w, sP[se*484 + o], M[se]);
        }

    const float EPSF = 2.2204460492503131e-16f;
    float res[12];
    #pragma unroll
    for (int s = 0; s < 2; ++s) {
        const float* Ms = M + s*10;
        // j = 0 : 1x1
        res[s*6 + 0] = fabsf(Ms[0]) + EPSF;
        // j = 1 : symmetric 2x2 [a b; b c]
        {
            float a = Ms[1], bq = Ms[2], c2 = Ms[3];
            float p1 = a + c2;
            float p2 = a*a + 2.f*bq*bq + c2*c2;
            float e1 = p1;
            float e2 = 0.5f*(p1*e1 - p2);
            res[s*6 + 1] = 10.f*(fabsf(e1) + EPSF);
            res[s*6 + 2] = 10.f*sqrtf(fabsf(e2) + EPSF);
        }
        // j = 2 : symmetric 3x3 [a b c; b d e; c e f]
        {
            float a = Ms[4], bq = Ms[5], cq = Ms[6], d = Ms[7], e = Ms[8], f = Ms[9];
            float p1 = a + d + f;
            float p2 = a*a + d*d + f*f + 2.f*(bq*bq + cq*cq + e*e);
            float p3 = a*a*a + d*d*d + f*f*f
                     + 3.f*(a*(bq*bq + cq*cq) + d*(bq*bq + e*e) + f*(cq*cq + e*e))
                     + 6.f*bq*cq*e;
            float e1 = p1;
            float e2 = 0.5f*(p1*e1 - p2);
            float e3 = (p1*e2 - p2*e1 + p3)*(1.f/3.f);
            res[s*6 + 3] = 100.f*(fabsf(e1) + EPSF);
            res[s*6 + 4] = 100.f*sqrtf(fabsf(e2) + EPSF);
            res[s*6 + 5] = 100.f*cbrtf(fabsf(e3) + EPSF);
        }
    }
    float* op = out + ((size_t)(b*HO + yo)*HO + xo)*12;
    #pragma unroll
    for (int ch = 0; ch < 12; ++ch) op[ch] = res[ch];
}

// ---------------- launcher ---------------------------------------------------
extern "C" void kernel_launch(void* const* d_in, const int* in_sizes, int n_in,
                              void* d_out, int out_size) {
    const float* in  = (const float*)d_in[0];
    const float* k0  = (const float*)d_in[1];
    const float* k1  = (const float*)d_in[2];
    const float* dgi = (const float*)d_in[3];
    float* out = (float*)d_out;

    factorize<<<1, 32>>>(k0, k1, dgi);

    dim3 g1(3, HH, BB);
    dim3 g2(48, 4, BB);
    // sigma 0 (7x7, R=3)
    stage1<3><<<g1, 256>>>(in, 0);
    stage2<3><<<g2, 256>>>(0);
    // sigma 1 (13x13, R=6) — reuses g_X scratch
    stage1<6><<<g1, 256>>>(in, 1);
    stage2<6><<<g2, 256>>>(1);

    stage3<<<dim3(12, 12, BB), 256>>>(out);
}

// round 4
// speedup vs baseline: 1.4119x; 1.4119x over previous
#include <cuda_runtime.h>
#include <math.h>

#define BB 4
#define HH 192
#define WW 192
#define CC 64
#define HO 186
#define BHW (BB*HH*WW)          /* 147456 */
#define NELEM (BB*HH*WW*CC)     /* 9437184 */

// ---------------- scratch (device globals; no allocs allowed) ----------------
__device__ float  g_X[3][NELEM];   // x-conv results, orders 0..2 (reused per sigma)
__device__ float  g_P[2*10*BHW];   // [(sigma*10+e)][b*H*W] channel-reduced products
__device__ float2 g_fxe[2][7];     // x-factors folded: (ord0, ord2) taps 0..R (R = center)
__device__ float  g_fxo[2][6];     // x-factor order1 taps 0..R-1 (antisym; center==0)
__device__ float4 g_fe[2][7];      // y-factors even maps: (L0=m0, L3=m3, L2=m2, L5=m5)
__device__ float2 g_fo[2][6];      // y-factors odd  maps: (L1=m1, L4=m4)
__device__ float  g_w2[49];        // integrator 7x7 = wy[i]*wx[j]

__device__ __forceinline__ float warp_sum(float v) {
    #pragma unroll
    for (int off = 16; off >= 1; off >>= 1)
        v += __shfl_xor_sync(0xffffffffu, v, off);
    return v;
}

// ---------------- factorization of the 2-D kernels into 1-D factors ----------
__device__ void factor_one(const float* K, int Ksz, int s) {
    const int R = (Ksz - 1) / 2;
    const int canon[3] = {0, 2, 5};          // canonical kernel per x-order (k=0,1,2)
    const int kxo[6]   = {0, 0, 1, 0, 1, 2}; // x-order of kernel m
    int   c0s[3];
    float fx[3][13];
    for (int o = 0; o < 3; ++o) {
        const float* Km = K + canon[o]*Ksz*Ksz*CC;
        int r0 = 0, c0 = 0; float best = -1.f;
        for (int i = 0; i < Ksz; ++i)
            for (int j = 0; j < Ksz; ++j) {
                float v = fabsf(Km[(i*Ksz + j)*CC]);
                if (v > best) { best = v; r0 = i; c0 = j; }
            }
        float piv = Km[(r0*Ksz + c0)*CC];
        for (int j = 0; j < Ksz; ++j) fx[o][j] = Km[(r0*Ksz + j)*CC] / piv;
        c0s[o] = c0;
    }
    for (int t = 0; t <= R; ++t) g_fxe[s][t] = make_float2(fx[0][t], fx[2][t]);
    for (int t = 0; t <  R; ++t) g_fxo[s][t] = fx[1][t];

    const float comb[6] = {1.f, 1.f, 1.f, 1.f, 1.41421356237309515f, 1.f}; // sqrt(C(j,k))
    float fy[6][13];
    for (int m = 0; m < 6; ++m) {
        int c0 = c0s[kxo[m]];
        for (int i = 0; i < Ksz; ++i)
            fy[m][i] = K[(m*Ksz*Ksz + i*Ksz + c0)*CC] * comb[m];
    }
    // evens in y: m0(L0), m3(L3), m2(L2), m5(L5); odds: m1(L1), m4(L4)
    for (int t = 0; t <= R; ++t)
        g_fe[s][t] = make_float4(fy[0][t], fy[3][t], fy[2][t], fy[5][t]);
    for (int t = 0; t <  R; ++t)
        g_fo[s][t] = make_float2(fy[1][t], fy[4][t]);
}

__global__ void factorize(const float* __restrict__ k0, const float* __restrict__ k1,
                          const float* __restrict__ dgi) {
    if (threadIdx.x != 0) return;
    factor_one(k0, 7, 0);
    factor_one(k1, 13, 1);
    // integrator: 7x7 rank-1, all channels identical (take c=0)
    int r0 = 0, c0 = 0; float best = -1.f;
    for (int i = 0; i < 7; ++i)
        for (int j = 0; j < 7; ++j) {
            float v = fabsf(dgi[(i*7 + j)*CC]);
            if (v > best) { best = v; r0 = i; c0 = j; }
        }
    float piv = dgi[(r0*7 + c0)*CC];
    for (int i = 0; i < 7; ++i)
        for (int j = 0; j < 7; ++j)
            g_w2[i*7 + j] = dgi[(i*7 + c0)*CC] * (dgi[(r0*7 + j)*CC] / piv);
}

// ---------------- stage 1: horizontal (x) convolution, orders 0..2 ----------
// Thread handles a float2 channel pair; symmetry folds 2K+1 taps into R sums/diffs.
template<int R>
__global__ void __launch_bounds__(256) stage1(const float* __restrict__ in, int sigma) {
    constexpr int K  = 2*R + 1;
    constexpr int XT = 64;
    __shared__ float2 s_in[(XT + 2*R)*32];
    const int b = blockIdx.z, yrow = blockIdx.y, x0 = blockIdx.x*XT;
    const int tid = threadIdx.x;
    const float2* rowv = (const float2*)(in + ((size_t)(b*HH + yrow)*WW)*CC);
    for (int t = tid; t < (XT + 2*R)*32; t += 256) {
        int xx = (t >> 5) - R + x0;
        int c2 = t & 31;
        s_in[t] = (xx >= 0 && xx < WW) ? rowv[xx*32 + c2] : make_float2(0.f, 0.f);
    }
    float2 fxe[R+1]; float fxo[R];
    #pragma unroll
    for (int t = 0; t <= R; ++t) fxe[t] = g_fxe[sigma][t];
    #pragma unroll
    for (int t = 0; t <  R; ++t) fxo[t] = g_fxo[sigma][t];
    __syncthreads();

    const int c2 = tid & 31, xg = tid >> 5;
    const size_t obase = ((size_t)(b*HH + yrow)*WW)*CC;
    float2* o0 = (float2*)&g_X[0][obase];
    float2* o1 = (float2*)&g_X[1][obase];
    float2* o2 = (float2*)&g_X[2][obase];
    #pragma unroll
    for (int xq = 0; xq < 8; ++xq) {
        int xi = xg*8 + xq;
        float2 a0 = {0.f,0.f}, a1 = {0.f,0.f}, a2 = {0.f,0.f};
        #pragma unroll
        for (int t = 0; t < R; ++t) {
            float2 u = s_in[(xi + t)*32 + c2];
            float2 v = s_in[(xi + K - 1 - t)*32 + c2];
            float sx = u.x + v.x, sy = u.y + v.y;
            float dx = u.x - v.x, dy = u.y - v.y;
            a0.x = fmaf(fxe[t].x, sx, a0.x); a0.y = fmaf(fxe[t].x, sy, a0.y);
            a2.x = fmaf(fxe[t].y, sx, a2.x); a2.y = fmaf(fxe[t].y, sy, a2.y);
            a1.x = fmaf(fxo[t],   dx, a1.x); a1.y = fmaf(fxo[t],   dy, a1.y);
        }
        float2 m = s_in[(xi + R)*32 + c2];
        a0.x = fmaf(fxe[R].x, m.x, a0.x); a0.y = fmaf(fxe[R].x, m.y, a0.y);
        a2.x = fmaf(fxe[R].y, m.x, a2.x); a2.y = fmaf(fxe[R].y, m.y, a2.y);
        int off = (x0 + xi)*32 + c2;
        o0[off] = a0; o1[off] = a1; o2[off] = a2;
    }
}

// ---- stage 2: vertical conv (6 L maps) + outer products + channel reduce ----
// Warp = one x column, all 64 channels (2 per lane via float2). Register ring
// over y with unroll-by-K (no shifts); folded coeffs in registers; one
// butterfly reduction per pixel.
template<int R, int SEGH, int NCH>
__global__ void __launch_bounds__(256) stage2(int sigma) {
    constexpr int K = 2*R + 1;
    static_assert(SEGH == NCH*K, "strip must be multiple of K");
    const int tid  = threadIdx.x;
    const int warp = tid >> 5, lane = tid & 31;
    const int b    = blockIdx.z;
    const int x    = blockIdx.x*8 + warp;
    const int ys   = blockIdx.y*SEGH;          // SEGH % K == 0 -> slots compile-time
    const int rs   = WW*32;                    // row stride in float2 units
    const size_t base = ((size_t)(b*HH*WW) + x)*32 + lane;
    const float2* X0 = (const float2*)g_X[0] + base;
    const float2* X1 = (const float2*)g_X[1] + base;
    const float2* X2 = (const float2*)g_X[2] + base;

    float4 fe[R+1]; float2 fo[R];
    #pragma unroll
    for (int t = 0; t <= R; ++t) fe[t] = g_fe[sigma][t];
    #pragma unroll
    for (int t = 0; t <  R; ++t) fo[t] = g_fo[sigma][t];

    const float2 Z2 = make_float2(0.f, 0.f);
    float2 r0[K], r1[K], r2[K];
    #pragma unroll
    for (int j = 0; j < K - 1; ++j) {            // preload rows ys-R+j
        int yy = ys - R + j;
        const int sl = (j + K - R) % K;
        bool ok = (yy >= 0 && yy < HH);
        r0[sl] = ok ? X0[(size_t)yy*rs] : Z2;
        r1[sl] = ok ? X1[(size_t)yy*rs] : Z2;
        r2[sl] = ok ? X2[(size_t)yy*rs] : Z2;
    }
    float* Pb = &g_P[(size_t)(sigma*10)*BHW + (size_t)b*HH*WW + x];

    int y = ys;
    for (int ch = 0; ch < NCH; ++ch) {
        #pragma unroll
        for (int i = 0; i < K; ++i, ++y) {
            {   // load row y+R into slot (i+R)%K
                const int slN = (i + R) % K;
                int yy = y + R;
                bool ok = yy < HH;
                r0[slN] = ok ? X0[(size_t)yy*rs] : Z2;
                r1[slN] = ok ? X1[(size_t)yy*rs] : Z2;
                r2[slN] = ok ? X2[(size_t)yy*rs] : Z2;
            }
            float2 L0=Z2, L1=Z2, L2=Z2, L3=Z2, L4=Z2, L5=Z2;
            #pragma unroll
            for (int j = 0; j < R; ++j) {
                const int sa = (i + j + (K - R)) % K;
                const int sb = (i + (K - 1 - j) + (K - R)) % K;
                float2 a0 = r0[sa], b0 = r0[sb];
                float2 a1 = r1[sa], b1 = r1[sb];
                float2 a2 = r2[sa], b2 = r2[sb];
                float s0x = a0.x + b0.x, s0y = a0.y + b0.y;
                float d0x = a0.x - b0.x, d0y = a0.y - b0.y;
                float s1x = a1.x + b1.x, s1y = a1.y + b1.y;
                float d1x = a1.x - b1.x, d1y = a1.y - b1.y;
                float s2x = a2.x + b2.x, s2y = a2.y + b2.y;
                L0.x = fmaf(fe[j].x, s0x, L0.x); L0.y = fmaf(fe[j].x, s0y, L0.y);
                L3.x = fmaf(fe[j].y, s0x, L3.x); L3.y = fmaf(fe[j].y, s0y, L3.y);
                L2.x = fmaf(fe[j].z, s1x, L2.x); L2.y = fmaf(fe[j].z, s1y, L2.y);
                L5.x = fmaf(fe[j].w, s2x, L5.x); L5.y = fmaf(fe[j].w, s2y, L5.y);
                L1.x = fmaf(fo[j].x, d0x, L1.x); L1.y = fmaf(fo[j].x, d0y, L1.y);
                L4.x = fmaf(fo[j].y, d1x, L4.x); L4.y = fmaf(fo[j].y, d1y, L4.y);
            }
            {   // center tap: slot == i  (odd maps have exact zero center)
                L0.x = fmaf(fe[R].x, r0[i].x, L0.x); L0.y = fmaf(fe[R].x, r0[i].y, L0.y);
                L3.x = fmaf(fe[R].y, r0[i].x, L3.x); L3.y = fmaf(fe[R].y, r0[i].y, L3.y);
                L2.x = fmaf(fe[R].z, r1[i].x, L2.x); L2.y = fmaf(fe[R].z, r1[i].y, L2.y);
                L5.x = fmaf(fe[R].w, r2[i].x, L5.x); L5.y = fmaf(fe[R].w, r2[i].y, L5.y);
            }
            float p0 = warp_sum(fmaf(L0.y, L0.y, L0.x*L0.x));
            float p1 = warp_sum(fmaf(L1.y, L1.y, L1.x*L1.x));
            float p2 = warp_sum(fmaf(L1.y, L2.y, L1.x*L2.x));
            float p3 = warp_sum(fmaf(L2.y, L2.y, L2.x*L2.x));
            float p4 = warp_sum(fmaf(L3.y, L3.y, L3.x*L3.x));
            float p5 = warp_sum(fmaf(L3.y, L4.y, L3.x*L4.x));
            float p6 = warp_sum(fmaf(L3.y, L5.y, L3.x*L5.x));
            float p7 = warp_sum(fmaf(L4.y, L4.y, L4.x*L4.x));
            float p8 = warp_sum(fmaf(L4.y, L5.y, L4.x*L5.x));
            float p9 = warp_sum(fmaf(L5.y, L5.y, L5.x*L5.x));
            if (lane == 0 && y < HH) {
                const int py = y*WW;
                Pb[(size_t)0*BHW + py] = p0;
                Pb[(size_t)1*BHW + py] = p1;
                Pb[(size_t)2*BHW + py] = p2;
                Pb[(size_t)3*BHW + py] = p3;
                Pb[(size_t)4*BHW + py] = p4;
                Pb[(size_t)5*BHW + py] = p5;
                Pb[(size_t)6*BHW + py] = p6;
                Pb[(size_t)7*BHW + py] = p7;
                Pb[(size_t)8*BHW + py] = p8;
                Pb[(size_t)9*BHW + py] = p9;
            }
        }
    }
}

// ---------------- stage 3: 7x7 VALID integration + Newton-identity ESPs -----
__global__ void __launch_bounds__(256) stage3(float* __restrict__ out) {
    __shared__ float sP[20*22*22];
    __shared__ float sw[49];
    const int tid = threadIdx.x;
    const int b = blockIdx.z;
    const int y0 = blockIdx.y*16, x0 = blockIdx.x*16;
    if (tid < 49) sw[tid] = g_w2[tid];
    for (int idx = tid; idx < 20*484; idx += 256) {
        int se  = idx / 484;
        int rem = idx - se*484;
        int r   = rem / 22;
        int cc2 = rem - r*22;
        int y = y0 + r, x = x0 + cc2;
        float v = 0.f;
        if (y < HH && x < WW)
            v = g_P[(size_t)se*BHW + (size_t)(b*HH + y)*WW + x];
        sP[idx] = v;
    }
    __syncthreads();
    const int ty = tid >> 4, tx = tid & 15;
    const int yo = y0 + ty, xo = x0 + tx;
    if (yo >= HO || xo >= HO) return;

    float M[20];
    #pragma unroll
    for (int se = 0; se < 20; ++se) M[se] = 0.f;
    #pragma unroll
    for (int i = 0; i < 7; ++i)
        #pragma unroll
        for (int j = 0; j < 7; ++j) {
            float w = sw[i*7 + j];
            int o = (ty + i)*22 + (tx + j);
            #pragma unroll
            for (int se = 0; se < 20; ++se)
                M[se] = fmaf(w, sP[se*484 + o], M[se]);
        }

    const float EPSF = 2.2204460492503131e-16f;
    float res[12];
    #pragma unroll
    for (int s = 0; s < 2; ++s) {
        const float* Ms = M + s*10;
        res[s*6 + 0] = fabsf(Ms[0]) + EPSF;
        {
            float a = Ms[1], bq = Ms[2], c2v = Ms[3];
            float p1 = a + c2v;
            float p2 = a*a + 2.f*bq*bq + c2v*c2v;
            float e1 = p1;
            float e2 = 0.5f*(p1*e1 - p2);
            res[s*6 + 1] = 10.f*(fabsf(e1) + EPSF);
            res[s*6 + 2] = 10.f*sqrtf(fabsf(e2) + EPSF);
        }
        {
            float a = Ms[4], bq = Ms[5], cq = Ms[6], d = Ms[7], e = Ms[8], f = Ms[9];
            float p1 = a + d + f;
            float p2 = a*a + d*d + f*f + 2.f*(bq*bq + cq*cq + e*e);
            float p3 = a*a*a + d*d*d + f*f*f
                     + 3.f*(a*(bq*bq + cq*cq) + d*(bq*bq + e*e) + f*(cq*cq + e*e))
                     + 6.f*bq*cq*e;
            float e1 = p1;
            float e2 = 0.5f*(p1*e1 - p2);
            float e3 = (p1*e2 - p2*e1 + p3)*(1.f/3.f);
            res[s*6 + 3] = 100.f*(fabsf(e1) + EPSF);
            res[s*6 + 4] = 100.f*sqrtf(fabsf(e2) + EPSF);
            res[s*6 + 5] = 100.f*cbrtf(fabsf(e3) + EPSF);
        }
    }
    float* op = out + ((size_t)(b*HO + yo)*HO + xo)*12;
    #pragma unroll
    for (int chn = 0; chn < 12; ++chn) op[chn] = res[chn];
}

// ---------------- launcher ---------------------------------------------------
extern "C" void kernel_launch(void* const* d_in, const int* in_sizes, int n_in,
                              void* d_out, int out_size) {
    const float* in  = (const float*)d_in[0];
    const float* k0  = (const float*)d_in[1];
    const float* k1  = (const float*)d_in[2];
    const float* dgi = (const float*)d_in[3];
    float* out = (float*)d_out;

    factorize<<<1, 32>>>(k0, k1, dgi);

    dim3 g1(3, HH, BB);
    dim3 g2(24, 4, BB);
    // sigma 0 (7x7, R=3): strips of 49 = 7*7
    stage1<3><<<g1, 256>>>(in, 0);
    stage2<3, 49, 7><<<g2, 256>>>(0);
    // sigma 1 (13x13, R=6): strips of 52 = 4*13 — reuses g_X scratch
    stage1<6><<<g1, 256>>>(in, 1);
    stage2<6, 52, 4><<<g2, 256>>>(1);

    stage3<<<dim3(12, 12, BB), 256>>>(out);
}

// round 5
// speedup vs baseline: 1.6086x; 1.1393x over previous
#include <cuda_runtime.h>
#include <math.h>

#define BB 4
#define HH 192
#define WW 192
#define CC 64
#define HO 186
#define BHW (BB*HH*WW)          /* 147456 */
#define NELEM (BB*HH*WW*CC)     /* 9437184 */

// ---------------- scratch (device globals; no allocs allowed) ----------------
__device__ float  g_X[3][NELEM];   // x-conv results, orders 0..2 (reused per sigma)
__device__ float  g_P[2*10*BHW];   // [(sigma*10+e)][b*H*W] channel-reduced products
__device__ float2 g_fxe[2][7];     // x-factors folded: (ord0, ord2) taps 0..R (R = center)
__device__ float  g_fxo[2][6];     // x-factor order1 taps 0..R-1 (antisym; center==0)
__device__ float4 g_fe[2][7];      // y-factors even maps: (L0=m0, L3=m3, L2=m2, L5=m5)
__device__ float2 g_fo[2][6];      // y-factors odd  maps: (L1=m1, L4=m4)
__device__ float  g_w2[49];        // integrator 7x7 = wy[i]*wx[j]

// ---------------- factorization of the 2-D kernels into 1-D factors ----------
__device__ void factor_one(const float* K, int Ksz, int s) {
    const int R = (Ksz - 1) / 2;
    const int canon[3] = {0, 2, 5};          // canonical kernel per x-order (k=0,1,2)
    const int kxo[6]   = {0, 0, 1, 0, 1, 2}; // x-order of kernel m
    int   c0s[3];
    float fx[3][13];
    for (int o = 0; o < 3; ++o) {
        const float* Km = K + canon[o]*Ksz*Ksz*CC;
        int r0 = 0, c0 = 0; float best = -1.f;
        for (int i = 0; i < Ksz; ++i)
            for (int j = 0; j < Ksz; ++j) {
                float v = fabsf(Km[(i*Ksz + j)*CC]);
                if (v > best) { best = v; r0 = i; c0 = j; }
            }
        float piv = Km[(r0*Ksz + c0)*CC];
        for (int j = 0; j < Ksz; ++j) fx[o][j] = Km[(r0*Ksz + j)*CC] / piv;
        c0s[o] = c0;
    }
    for (int t = 0; t <= R; ++t) g_fxe[s][t] = make_float2(fx[0][t], fx[2][t]);
    for (int t = 0; t <  R; ++t) g_fxo[s][t] = fx[1][t];

    const float comb[6] = {1.f, 1.f, 1.f, 1.f, 1.41421356237309515f, 1.f}; // sqrt(C(j,k))
    float fy[6][13];
    for (int m = 0; m < 6; ++m) {
        int c0 = c0s[kxo[m]];
        for (int i = 0; i < Ksz; ++i)
            fy[m][i] = K[(m*Ksz*Ksz + i*Ksz + c0)*CC] * comb[m];
    }
    // evens in y: m0(L0), m3(L3), m2(L2), m5(L5); odds: m1(L1), m4(L4)
    for (int t = 0; t <= R; ++t)
        g_fe[s][t] = make_float4(fy[0][t], fy[3][t], fy[2][t], fy[5][t]);
    for (int t = 0; t <  R; ++t)
        g_fo[s][t] = make_float2(fy[1][t], fy[4][t]);
}

__global__ void factorize(const float* __restrict__ k0, const float* __restrict__ k1,
                          const float* __restrict__ dgi) {
    if (threadIdx.x != 0) return;
    factor_one(k0, 7, 0);
    factor_one(k1, 13, 1);
    // integrator: 7x7 rank-1, all channels identical (take c=0)
    int r0 = 0, c0 = 0; float best = -1.f;
    for (int i = 0; i < 7; ++i)
        for (int j = 0; j < 7; ++j) {
            float v = fabsf(dgi[(i*7 + j)*CC]);
            if (v > best) { best = v; r0 = i; c0 = j; }
        }
    float piv = dgi[(r0*7 + c0)*CC];
    for (int i = 0; i < 7; ++i)
        for (int j = 0; j < 7; ++j)
            g_w2[i*7 + j] = dgi[(i*7 + c0)*CC] * (dgi[(r0*7 + j)*CC] / piv);
}

// ---------------- stage 1: horizontal (x) convolution, orders 0..2 ----------
// Thread handles a float2 channel pair; symmetry folds 2K+1 taps into R sums/diffs.
template<int R>
__global__ void __launch_bounds__(256) stage1(const float* __restrict__ in, int sigma) {
    constexpr int K  = 2*R + 1;
    constexpr int XT = 64;
    __shared__ float2 s_in[(XT + 2*R)*32];
    const int b = blockIdx.z, yrow = blockIdx.y, x0 = blockIdx.x*XT;
    const int tid = threadIdx.x;
    const float2* rowv = (const float2*)(in + ((size_t)(b*HH + yrow)*WW)*CC);
    for (int t = tid; t < (XT + 2*R)*32; t += 256) {
        int xx = (t >> 5) - R + x0;
        int c2 = t & 31;
        s_in[t] = (xx >= 0 && xx < WW) ? rowv[xx*32 + c2] : make_float2(0.f, 0.f);
    }
    float2 fxe[R+1]; float fxo[R];
    #pragma unroll
    for (int t = 0; t <= R; ++t) fxe[t] = g_fxe[sigma][t];
    #pragma unroll
    for (int t = 0; t <  R; ++t) fxo[t] = g_fxo[sigma][t];
    __syncthreads();

    const int c2 = tid & 31, xg = tid >> 5;
    const size_t obase = ((size_t)(b*HH + yrow)*WW)*CC;
    float2* o0 = (float2*)&g_X[0][obase];
    float2* o1 = (float2*)&g_X[1][obase];
    float2* o2 = (float2*)&g_X[2][obase];
    #pragma unroll
    for (int xq = 0; xq < 8; ++xq) {
        int xi = xg*8 + xq;
        float2 a0 = {0.f,0.f}, a1 = {0.f,0.f}, a2 = {0.f,0.f};
        #pragma unroll
        for (int t = 0; t < R; ++t) {
            float2 u = s_in[(xi + t)*32 + c2];
            float2 v = s_in[(xi + K - 1 - t)*32 + c2];
            float sx = u.x + v.x, sy = u.y + v.y;
            float dx = u.x - v.x, dy = u.y - v.y;
            a0.x = fmaf(fxe[t].x, sx, a0.x); a0.y = fmaf(fxe[t].x, sy, a0.y);
            a2.x = fmaf(fxe[t].y, sx, a2.x); a2.y = fmaf(fxe[t].y, sy, a2.y);
            a1.x = fmaf(fxo[t],   dx, a1.x); a1.y = fmaf(fxo[t],   dy, a1.y);
        }
        float2 m = s_in[(xi + R)*32 + c2];
        a0.x = fmaf(fxe[R].x, m.x, a0.x); a0.y = fmaf(fxe[R].x, m.y, a0.y);
        a2.x = fmaf(fxe[R].y, m.x, a2.x); a2.y = fmaf(fxe[R].y, m.y, a2.y);
        int off = (x0 + xi)*32 + c2;
        o0[off] = a0; o1[off] = a1; o2[off] = a2;
    }
}

// ---- stage 2: vertical conv (6 L maps) + outer products + channel reduce ----
// Warp = one x column, all 64 channels (2 per lane via float2). Register ring
// over y with unroll-by-K; split-butterfly reduces 10 entries in ~44 instrs,
// leaving entry totals distributed across lanes -> one predicated STG.
template<int R, int SEGH, int NCH>
__global__ void __launch_bounds__(256) stage2(int sigma) {
    constexpr int K = 2*R + 1;
    static_assert(SEGH == NCH*K, "strip must be multiple of K");
    const int tid  = threadIdx.x;
    const int warp = tid >> 5, lane = tid & 31;
    const int b    = blockIdx.z;
    const int x    = blockIdx.x*8 + warp;
    const int ys   = blockIdx.y*SEGH;          // SEGH % K == 0 -> slots compile-time
    const int rs   = WW*32;                    // row stride in float2 units
    const size_t base = ((size_t)(b*HH*WW) + x)*32 + lane;
    const float2* X0 = (const float2*)g_X[0] + base;
    const float2* X1 = (const float2*)g_X[1] + base;
    const float2* X2 = (const float2*)g_X[2] + base;

    float4 fe[R+1]; float2 fo[R];
    #pragma unroll
    for (int t = 0; t <= R; ++t) fe[t] = g_fe[sigma][t];
    #pragma unroll
    for (int t = 0; t <  R; ++t) fo[t] = g_fo[sigma][t];

    // --- per-lane reduction routing (computed once) ---
    const bool h4 = (lane & 16) != 0;
    const bool h3 = (lane & 8)  != 0;
    const bool h2 = (lane & 4)  != 0;
    const bool h1 = (lane & 2)  != 0;
    const bool two = (!h3) && (!h2);           // class holding 2 entries at L3
    const int  m4 = lane & 15;
    const int  f  = (m4==0) ? 0 : (m4==2) ? 1 : (m4==4) ? 2 : (m4==8) ? 3 : 4;
    const int  eidx = (h4 ? 5 : 0) + f;
    const bool writer = (m4==0 || m4==2 || m4==4 || m4==8 || m4==12);
    float* PbE = &g_P[(size_t)(sigma*10 + eidx)*BHW + (size_t)b*HH*WW + x];

    const float2 Z2 = make_float2(0.f, 0.f);
    float2 r0[K], r1[K], r2[K];
    #pragma unroll
    for (int j = 0; j < K - 1; ++j) {            // preload rows ys-R+j
        int yy = ys - R + j;
        const int sl = (j + K - R) % K;
        bool ok = (yy >= 0 && yy < HH);
        r0[sl] = ok ? X0[(size_t)yy*rs] : Z2;
        r1[sl] = ok ? X1[(size_t)yy*rs] : Z2;
        r2[sl] = ok ? X2[(size_t)yy*rs] : Z2;
    }

    int y = ys;
    for (int ch = 0; ch < NCH; ++ch) {
        #pragma unroll
        for (int i = 0; i < K; ++i, ++y) {
            {   // load row y+R into slot (i+R)%K
                const int slN = (i + R) % K;
                int yy = y + R;
                bool ok = yy < HH;
                r0[slN] = ok ? X0[(size_t)yy*rs] : Z2;
                r1[slN] = ok ? X1[(size_t)yy*rs] : Z2;
                r2[slN] = ok ? X2[(size_t)yy*rs] : Z2;
            }
            float2 L0=Z2, L1=Z2, L2=Z2, L3=Z2, L4=Z2, L5=Z2;
            #pragma unroll
            for (int j = 0; j < R; ++j) {
                const int sa = (i + j + (K - R)) % K;
                const int sb = (i + (K - 1 - j) + (K - R)) % K;
                float2 a0 = r0[sa], b0 = r0[sb];
                float2 a1 = r1[sa], b1 = r1[sb];
                float2 a2 = r2[sa], b2 = r2[sb];
                float s0x = a0.x + b0.x, s0y = a0.y + b0.y;
                float d0x = a0.x - b0.x, d0y = a0.y - b0.y;
                float s1x = a1.x + b1.x, s1y = a1.y + b1.y;
                float d1x = a1.x - b1.x, d1y = a1.y - b1.y;
                float s2x = a2.x + b2.x, s2y = a2.y + b2.y;
                L0.x = fmaf(fe[j].x, s0x, L0.x); L0.y = fmaf(fe[j].x, s0y, L0.y);
                L3.x = fmaf(fe[j].y, s0x, L3.x); L3.y = fmaf(fe[j].y, s0y, L3.y);
                L2.x = fmaf(fe[j].z, s1x, L2.x); L2.y = fmaf(fe[j].z, s1y, L2.y);
                L5.x = fmaf(fe[j].w, s2x, L5.x); L5.y = fmaf(fe[j].w, s2y, L5.y);
                L1.x = fmaf(fo[j].x, d0x, L1.x); L1.y = fmaf(fo[j].x, d0y, L1.y);
                L4.x = fmaf(fo[j].y, d1x, L4.x); L4.y = fmaf(fo[j].y, d1y, L4.y);
            }
            {   // center tap: slot == i  (odd maps have exact zero center)
                L0.x = fmaf(fe[R].x, r0[i].x, L0.x); L0.y = fmaf(fe[R].x, r0[i].y, L0.y);
                L3.x = fmaf(fe[R].y, r0[i].x, L3.x); L3.y = fmaf(fe[R].y, r0[i].y, L3.y);
                L2.x = fmaf(fe[R].z, r1[i].x, L2.x); L2.y = fmaf(fe[R].z, r1[i].y, L2.y);
                L5.x = fmaf(fe[R].w, r2[i].x, L5.x); L5.y = fmaf(fe[R].w, r2[i].y, L5.y);
            }
            // per-lane products (2 channels folded)
            float p0 = fmaf(L0.y, L0.y, L0.x*L0.x);
            float p1 = fmaf(L1.y, L1.y, L1.x*L1.x);
            float p2 = fmaf(L1.y, L2.y, L1.x*L2.x);
            float p3 = fmaf(L2.y, L2.y, L2.x*L2.x);
            float p4 = fmaf(L3.y, L3.y, L3.x*L3.x);
            float p5 = fmaf(L3.y, L4.y, L3.x*L4.x);
            float p6 = fmaf(L3.y, L5.y, L3.x*L5.x);
            float p7 = fmaf(L4.y, L4.y, L4.x*L4.x);
            float p8 = fmaf(L4.y, L5.y, L4.x*L5.x);
            float p9 = fmaf(L5.y, L5.y, L5.x*L5.x);

            // --- split-butterfly: 10 entries, halving entry set each level ---
            // L0 (xor16): keep e0-4 (h4=0) or e5-9 (h4=1)
            float v0, v1, v2, v3, v4;
            {
                float q, t;
                q = h4 ? p0 : p5; t = __shfl_xor_sync(0xffffffffu, q, 16); v0 = (h4 ? p5 : p0) + t;
                q = h4 ? p1 : p6; t = __shfl_xor_sync(0xffffffffu, q, 16); v1 = (h4 ? p6 : p1) + t;
                q = h4 ? p2 : p7; t = __shfl_xor_sync(0xffffffffu, q, 16); v2 = (h4 ? p7 : p2) + t;
                q = h4 ? p3 : p8; t = __shfl_xor_sync(0xffffffffu, q, 16); v3 = (h4 ? p8 : p3) + t;
                q = h4 ? p4 : p9; t = __shfl_xor_sync(0xffffffffu, q, 16); v4 = (h4 ? p9 : p4) + t;
            }
            // L1 (xor8): 5 -> {0,1,2} (h3=0) / {3,4} (h3=1)
            float w0, w1, w2;
            {
                float q0 = h3 ? v0 : v3;
                float q1 = h3 ? v1 : v4;
                float q2 = v2;
                float t0 = __shfl_xor_sync(0xffffffffu, q0, 8);
                float t1 = __shfl_xor_sync(0xffffffffu, q1, 8);
                float t2 = __shfl_xor_sync(0xffffffffu, q2, 8);
                if (!h3) { w0 = v0 + t0; w1 = v1 + t1; w2 = v2 + t2; }
                else     { w0 = v3 + t0; w1 = v4 + t1; w2 = 0.f; }
            }
            // L2 (xor4): {0,1}/{2} for h3=0; {a}/{b} for h3=1
            float u0, u1;
            {
                float q0 = h2 ? w0 : (h3 ? w1 : w2);
                float q1 = w1;
                float t0 = __shfl_xor_sync(0xffffffffu, q0, 4);
                float t1 = __shfl_xor_sync(0xffffffffu, q1, 4);
                if (!h3) {
                    if (!h2) { u0 = w0 + t0; u1 = w1 + t1; }
                    else     { u0 = w2 + t0; u1 = 0.f; }
                } else {
                    u0 = (h2 ? w1 : w0) + t0; u1 = 0.f;
                }
            }
            // L3 (xor2): split remaining pair classes; singles reduce
            float z;
            {
                float q = two ? (h1 ? u0 : u1) : u0;
                float t = __shfl_xor_sync(0xffffffffu, q, 2);
                z = (two ? (h1 ? u1 : u0) : u0) + t;
            }
            // L4 (xor1)
            z += __shfl_xor_sync(0xffffffffu, z, 1);

            if (writer && y < HH)
                PbE[y*WW] = z;
        }
    }
}

// ---------------- stage 3: 7x7 VALID integration + Newton-identity ESPs -----
__global__ void __launch_bounds__(256) stage3(float* __restrict__ out) {
    __shared__ float sP[20*22*22];
    __shared__ float sw[49];
    const int tid = threadIdx.x;
    const int b = blockIdx.z;
    const int y0 = blockIdx.y*16, x0 = blockIdx.x*16;
    if (tid < 49) sw[tid] = g_w2[tid];
    for (int idx = tid; idx < 20*484; idx += 256) {
        int se  = idx / 484;
        int rem = idx - se*484;
        int r   = rem / 22;
        int cc2 = rem - r*22;
        int y = y0 + r, x = x0 + cc2;
        float v = 0.f;
        if (y < HH && x < WW)
            v = g_P[(size_t)se*BHW + (size_t)(b*HH + y)*WW + x];
        sP[idx] = v;
    }
    __syncthreads();
    const int ty = tid >> 4, tx = tid & 15;
    const int yo = y0 + ty, xo = x0 + tx;
    if (yo >= HO || xo >= HO) return;

    float M[20];
    #pragma unroll
    for (int se = 0; se < 20; ++se) M[se] = 0.f;
    #pragma unroll
    for (int i = 0; i < 7; ++i)
        #pragma unroll
        for (int j = 0; j < 7; ++j) {
            float w = sw[i*7 + j];
            int o = (ty + i)*22 + (tx + j);
            #pragma unroll
            for (int se = 0; se < 20; ++se)
                M[se] = fmaf(w, sP[se*484 + o], M[se]);
        }

    const float EPSF = 2.2204460492503131e-16f;
    float res[12];
    #pragma unroll
    for (int s = 0; s < 2; ++s) {
        const float* Ms = M + s*10;
        res[s*6 + 0] = fabsf(Ms[0]) + EPSF;
        {
            float a = Ms[1], bq = Ms[2], c2v = Ms[3];
            float p1 = a + c2v;
            float p2 = a*a + 2.f*bq*bq + c2v*c2v;
            float e1 = p1;
            float e2 = 0.5f*(p1*e1 - p2);
            res[s*6 + 1] = 10.f*(fabsf(e1) + EPSF);
            res[s*6 + 2] = 10.f*sqrtf(fabsf(e2) + EPSF);
        }
        {
            float a = Ms[4], bq = Ms[5], cq = Ms[6], d = Ms[7], e = Ms[8], f = Ms[9];
            float p1 = a + d + f;
            float p2 = a*a + d*d + f*f + 2.f*(bq*bq + cq*cq + e*e);
            float p3 = a*a*a + d*d*d + f*f*f
                     + 3.f*(a*(bq*bq + cq*cq) + d*(bq*bq + e*e) + f*(cq*cq + e*e))
                     + 6.f*bq*cq*e;
            float e1 = p1;
            float e2 = 0.5f*(p1*e1 - p2);
            float e3 = (p1*e2 - p2*e1 + p3)*(1.f/3.f);
            res[s*6 + 3] = 100.f*(fabsf(e1) + EPSF);
            res[s*6 + 4] = 100.f*sqrtf(fabsf(e2) + EPSF);
            res[s*6 + 5] = 100.f*cbrtf(fabsf(e3) + EPSF);
        }
    }
    float* op = out + ((size_t)(b*HO + yo)*HO + xo)*12;
    #pragma unroll
    for (int chn = 0; chn < 12; ++chn) op[chn] = res[chn];
}

// ---------------- launcher ---------------------------------------------------
extern "C" void kernel_launch(void* const* d_in, const int* in_sizes, int n_in,
                              void* d_out, int out_size) {
    const float* in  = (const float*)d_in[0];
    const float* k0  = (const float*)d_in[1];
    const float* k1  = (const float*)d_in[2];
    const float* dgi = (const float*)d_in[3];
    float* out = (float*)d_out;

    factorize<<<1, 32>>>(k0, k1, dgi);

    dim3 g1(3, HH, BB);
    dim3 g2(24, 4, BB);
    // sigma 0 (7x7, R=3): strips of 49 = 7*7
    stage1<3><<<g1, 256>>>(in, 0);
    stage2<3, 49, 7><<<g2, 256>>>(0);
    // sigma 1 (13x13, R=6): strips of 52 = 4*13 — reuses g_X scratch
    stage1<6><<<g1, 256>>>(in, 1);
    stage2<6, 52, 4><<<g2, 256>>>(1);

    stage3<<<dim3(12, 12, BB), 256>>>(out);
}